// round 17
// baseline (speedup 1.0000x reference)
#include <cuda_runtime.h>
#include <cstdint>

#define DIM        64
#define VECS       16                  // DIM/4 float4 per row
#define NBC        50000               // n_bicliques (fixed by problem)
#define NUSR_MAX   100000              // n_users upper bound
#define NNZ_MAX    2500000             // edge capacity (problem uses 2M)

// Scratch (device globals: allowed; no allocation)
__device__ float g_biclique[NBC * DIM];     // stage-1 output, NORMALIZED
__device__ int   g_cnt[NUSR_MAX];           // row degrees (reused per stage)
__device__ int   g_off[NUSR_MAX];           // exclusive scan of degrees
__device__ int   g_cursor[NUSR_MAX];        // scatter cursors (= off at start)
__device__ int   g_perm[NNZ_MAX];           // edge ids grouped by row

// ---------------------------------------------------------------------------
// Zero the degree array for n rows.
// ---------------------------------------------------------------------------
__global__ void zero_cnt_kernel(int n) {
    int i = blockIdx.x * blockDim.x + threadIdx.x;
    if (i < n) g_cnt[i] = 0;
}

// ---------------------------------------------------------------------------
// Histogram: g_cnt[rows[e]]++  (int atomics, spread addresses -> fast)
// ---------------------------------------------------------------------------
__global__ void hist_kernel(const int* __restrict__ rows, int nnz) {
    int e = blockIdx.x * blockDim.x + threadIdx.x;
    if (e < nnz) atomicAdd(&g_cnt[__ldg(&rows[e])], 1);
}

// ---------------------------------------------------------------------------
// Single-block exclusive scan of g_cnt[0..n) -> g_off, g_cursor.
// 1024 threads, warp-shuffle scan per 1024-chunk, carry in shared.
// ---------------------------------------------------------------------------
__global__ void __launch_bounds__(1024)
scan_kernel(int n) {
    __shared__ int warp_sums[32];
    __shared__ int s_carry;
    int tid = threadIdx.x;
    int lane = tid & 31, wid = tid >> 5;
    if (tid == 0) s_carry = 0;
    __syncthreads();
    for (int base = 0; base < n; base += 1024) {
        int i = base + tid;
        int x = (i < n) ? g_cnt[i] : 0;
        // inclusive warp scan
        int v = x;
        #pragma unroll
        for (int d = 1; d < 32; d <<= 1) {
            int t = __shfl_up_sync(0xFFFFFFFFu, v, d);
            if (lane >= d) v += t;
        }
        if (lane == 31) warp_sums[wid] = v;
        __syncthreads();
        if (wid == 0) {
            int w = warp_sums[lane];
            #pragma unroll
            for (int d = 1; d < 32; d <<= 1) {
                int t = __shfl_up_sync(0xFFFFFFFFu, w, d);
                if (lane >= d) w += t;
            }
            warp_sums[lane] = w;
        }
        __syncthreads();
        int warp_off = (wid == 0) ? 0 : warp_sums[wid - 1];
        int excl = (v - x) + warp_off + s_carry;
        if (i < n) { g_off[i] = excl; g_cursor[i] = excl; }
        __syncthreads();                 // everyone done reading s_carry
        if (tid == 1023) s_carry = excl + x;   // chunk total carried forward
        __syncthreads();
    }
}

// ---------------------------------------------------------------------------
// Scatter edge ids into per-row segments: perm[off[r] + k] = e
// ---------------------------------------------------------------------------
__global__ void scatter_perm_kernel(const int* __restrict__ rows, int nnz) {
    int e = blockIdx.x * blockDim.x + threadIdx.x;
    if (e >= nnz) return;
    int r = __ldg(&rows[e]);
    int p = atomicAdd(&g_cursor[r], 1);
    g_perm[p] = e;
}

// ---------------------------------------------------------------------------
// Gather-reduce one output row per 16-lane group, one float4 slice per lane.
// acc = mean over the row's edges of src[cols[e]]; single write, no atomics.
// ---------------------------------------------------------------------------
__device__ __forceinline__ void gather_row(const float4* __restrict__ src,
                                           float4* __restrict__ dst,
                                           const int* __restrict__ cols,
                                           int row, int lane) {
    int start = g_off[row];
    int cnt   = g_cnt[row];
    int end   = start + cnt;
    float4 acc = make_float4(0.f, 0.f, 0.f, 0.f);
    #pragma unroll 4
    for (int j = start; j < end; j++) {
        int e = __ldg(&g_perm[j]);
        int c = __ldg(&cols[e]);
        float4 v = src[(long long)c * VECS + lane];
        acc.x += v.x; acc.y += v.y; acc.z += v.z; acc.w += v.w;
    }
    float inv = (cnt > 0) ? (1.0f / (float)cnt) : 1.0f;
    acc.x *= inv; acc.y *= inv; acc.z *= inv; acc.w *= inv;
    dst[(long long)row * VECS + lane] = acc;
}

// Stage 1: item_emb -> g_biclique (normalized at write)
__global__ void __launch_bounds__(256)
gather1_kernel(const float4* __restrict__ item_emb,
               const int* __restrict__ cols, int n_rows) {
    int g = blockIdx.x * blockDim.x + threadIdx.x;
    int lane = g & 15, row = g >> 4;
    if (row >= n_rows) return;
    gather_row(item_emb, reinterpret_cast<float4*>(g_biclique), cols, row, lane);
}

// Stage 2: g_biclique -> out (normalized at write)
__global__ void __launch_bounds__(256)
gather2_kernel(float4* __restrict__ out,
               const int* __restrict__ cols, int n_rows) {
    int g = blockIdx.x * blockDim.x + threadIdx.x;
    int lane = g & 15, row = g >> 4;
    if (row >= n_rows) return;
    gather_row(reinterpret_cast<const float4*>(g_biclique), out, cols, row, lane);
}

// ---------------------------------------------------------------------------
// Launch
// Inputs (metadata order): user_emb, item_emb, hv_rows, hv_cols, hu_rows,
//                          hu_cols, n_bicliques, n_users
// ---------------------------------------------------------------------------
extern "C" void kernel_launch(void* const* d_in, const int* in_sizes, int n_in,
                              void* d_out, int out_size) {
    const float4* item_emb = (const float4*)d_in[1];
    const int* hv_rows = (const int*)d_in[2];
    const int* hv_cols = (const int*)d_in[3];
    const int* hu_rows = (const int*)d_in[4];
    const int* hu_cols = (const int*)d_in[5];
    int nnz1 = in_sizes[2];
    int nnz2 = in_sizes[4];
    float4* out = (float4*)d_out;
    int n_users = out_size / DIM;

    int eb1 = (nnz1 + 255) / 256;
    int eb2 = (nnz2 + 255) / 256;

    // ---- Stage 1: CSR build over bicliques, then gather-reduce ----
    zero_cnt_kernel<<<(NBC + 255) / 256, 256>>>(NBC);
    hist_kernel<<<eb1, 256>>>(hv_rows, nnz1);
    scan_kernel<<<1, 1024>>>(NBC);
    scatter_perm_kernel<<<eb1, 256>>>(hv_rows, nnz1);
    gather1_kernel<<<(NBC * VECS + 255) / 256, 256>>>(item_emb, hv_cols, NBC);

    // ---- Stage 2: CSR build over users, then gather-reduce ----
    zero_cnt_kernel<<<(n_users + 255) / 256, 256>>>(n_users);
    hist_kernel<<<eb2, 256>>>(hu_rows, nnz2);
    scan_kernel<<<1, 1024>>>(n_users);
    scatter_perm_kernel<<<eb2, 256>>>(hu_rows, nnz2);
    gather2_kernel<<<(n_users * VECS + 255) / 256, 256>>>(out, hu_cols, n_users);
}